// round 8
// baseline (speedup 1.0000x reference)
#include <cuda_runtime.h>
#include <math.h>

#define BATCH 64
#define MOLA  50
#define PROA  500
#define HID   32
#define HEADS 8
#define NMOL  (BATCH * MOLA)          // 3200
#define NPRO  (BATCH * PROA)          // 32000
#define NPAIR ((size_t)NMOL * PROA)   // 1,600,000

// Scratch (allocation-free rule: __device__ globals)
__device__ float g_Amu [NMOL * HEADS];
__device__ float g_Asig[NMOL * HEADS];
__device__ float g_Pmu [NPRO * HEADS];
__device__ float g_Psig[NPRO * HEADS];
__device__ float g_ymol[NMOL * HEADS];

// ---------------------------------------------------------------------------
// Kernel 1: per-atom projections. One thread per (row, head): 281,600 threads,
// 8x the parallelism of one-thread-per-row; short dep chains, ~32 regs.
//   A_mu[m,h]  = b_mu[h]  + sum_k mol[m,k] * W_mu[k,h]
//   P_mu[j,h]  =            sum_k (pro[j,k]*spat[j,k]) * W_mu[32+k,h]
// ---------------------------------------------------------------------------
__global__ __launch_bounds__(256)
void proj_kernel(const float* __restrict__ mol_feats,
                 const float* __restrict__ pro_feats,
                 const float* __restrict__ spat,
                 const float* __restrict__ Wsig,
                 const float* __restrict__ bsig,
                 const float* __restrict__ Wmu,
                 const float* __restrict__ bmu)
{
    __shared__ float sWmu[2 * HID * HEADS];   // 512 floats each
    __shared__ float sWsig[2 * HID * HEADS];
    for (int i = threadIdx.x; i < 2 * HID * HEADS; i += blockDim.x) {
        sWmu[i]  = Wmu[i];
        sWsig[i] = Wsig[i];
    }
    __syncthreads();

    const int t = blockIdx.x * blockDim.x + threadIdx.x;
    const int r = t >> 3;          // row
    const int h = t & 7;           // head
    if (r >= NMOL + NPRO) return;

    const bool isMol = (r < NMOL);
    const int  j     = isMol ? r : (r - NMOL);

    float accm = isMol ? bmu[h]  : 0.f;
    float accs = isMol ? bsig[h] : 0.f;

    // weight column h; mol rows use W[0:32], pro rows use W[32:64]
    const float* wm = (isMol ? sWmu  : (sWmu  + HID * HEADS)) + h;
    const float* ws = (isMol ? sWsig : (sWsig + HID * HEADS)) + h;

    const float4* fsrc = isMol ? (const float4*)(mol_feats + (size_t)r * HID)
                               : (const float4*)(pro_feats + (size_t)j * HID);
    const float4* ssrc = isMol ? (const float4*)nullptr
                               : (const float4*)(spat + (size_t)j * HID);

    #pragma unroll
    for (int c = 0; c < HID / 4; c++) {
        float4 f4 = fsrc[c];
        if (!isMol) {
            float4 s4 = ssrc[c];
            f4.x *= s4.x; f4.y *= s4.y; f4.z *= s4.z; f4.w *= s4.w;
        }
        const int k = c * 4;
        accm = fmaf(f4.x, wm[(k + 0) * HEADS], accm);
        accm = fmaf(f4.y, wm[(k + 1) * HEADS], accm);
        accm = fmaf(f4.z, wm[(k + 2) * HEADS], accm);
        accm = fmaf(f4.w, wm[(k + 3) * HEADS], accm);
        accs = fmaf(f4.x, ws[(k + 0) * HEADS], accs);
        accs = fmaf(f4.y, ws[(k + 1) * HEADS], accs);
        accs = fmaf(f4.z, ws[(k + 2) * HEADS], accs);
        accs = fmaf(f4.w, ws[(k + 3) * HEADS], accs);
    }

    if (isMol) {
        g_Amu [(size_t)r * HEADS + h] = accm;
        g_Asig[(size_t)r * HEADS + h] = accs;
    } else {
        g_Pmu [(size_t)j * HEADS + h] = accm;
        g_Psig[(size_t)j * HEADS + h] = accs;
    }
}

// ---------------------------------------------------------------------------
// Kernel 2: per-pair mu/sigma + per-mol-atom sum of mu.
// Block = (complex b, chunk of 5 mol atoms): 640 blocks x 256 threads.
// The complex's P-table (500 x 8 x 2 floats = 32 KB) is staged in smem ONCE
// per block (L2 reads drop 102 MB -> 20 MB), stored as 4 separate float4[500]
// arrays (head-lo / head-hi for mu and sigma) -> 16B lane stride, bank-
// conflict-free LDS.128.
// Branchless ELU (exp(x) >= x+1 with equality at 0; clamp arg for x>0):
//   mu    = max(x + 1.0, __expf(min(x,0)))
//   sigma = max(x + 1.1, __expf(min(x,0)) + 0.1)
// ---------------------------------------------------------------------------
#define CHUNK_MOL 5
#define NCHUNK (MOLA / CHUNK_MOL)     // 10
#define PAIR_THREADS 256

__global__ __launch_bounds__(PAIR_THREADS)
void pairs_kernel(float* __restrict__ out_mu, float* __restrict__ out_sig)
{
    __shared__ float4 sPmuLo[PROA];   // 8 KB each, 32 KB total
    __shared__ float4 sPmuHi[PROA];
    __shared__ float4 sPsLo [PROA];
    __shared__ float4 sPsHi [PROA];
    __shared__ float  swarp[PAIR_THREADS / 32][HEADS];

    const int b     = blockIdx.x / NCHUNK;
    const int chunk = blockIdx.x % NCHUNK;
    const int tid   = threadIdx.x;

    // Stage the complex's P-tables into smem (coalesced float4 loads).
    for (int j = tid; j < PROA; j += PAIR_THREADS) {
        const float4* pm = (const float4*)(g_Pmu  + ((size_t)b * PROA + j) * HEADS);
        const float4* ps = (const float4*)(g_Psig + ((size_t)b * PROA + j) * HEADS);
        sPmuLo[j] = pm[0];
        sPmuHi[j] = pm[1];
        sPsLo [j] = ps[0];
        sPsHi [j] = ps[1];
    }
    __syncthreads();

    const int wid = tid >> 5;
    const int lid = tid & 31;

    #pragma unroll 1
    for (int ma = 0; ma < CHUNK_MOL; ma++) {
        const int m = b * MOLA + chunk * CHUNK_MOL + ma;

        float am[HEADS], as_[HEADS];
        {
            const float4 a0 = ((const float4*)(g_Amu  + (size_t)m * HEADS))[0];
            const float4 a1 = ((const float4*)(g_Amu  + (size_t)m * HEADS))[1];
            const float4 s0 = ((const float4*)(g_Asig + (size_t)m * HEADS))[0];
            const float4 s1 = ((const float4*)(g_Asig + (size_t)m * HEADS))[1];
            am[0]=a0.x; am[1]=a0.y; am[2]=a0.z; am[3]=a0.w;
            am[4]=a1.x; am[5]=a1.y; am[6]=a1.z; am[7]=a1.w;
            as_[0]=s0.x; as_[1]=s0.y; as_[2]=s0.z; as_[3]=s0.w;
            as_[4]=s1.x; as_[5]=s1.y; as_[6]=s1.z; as_[7]=s1.w;
        }

        float acc[HEADS];
        #pragma unroll
        for (int h = 0; h < HEADS; h++) acc[h] = 0.f;

        for (int j0 = tid; j0 < PROA; j0 += PAIR_THREADS) {
            const float4 pm0 = sPmuLo[j0];
            const float4 pm1 = sPmuHi[j0];
            const float4 ps0 = sPsLo [j0];
            const float4 ps1 = sPsHi [j0];

            const float xm[HEADS] = { am[0]+pm0.x, am[1]+pm0.y, am[2]+pm0.z, am[3]+pm0.w,
                                      am[4]+pm1.x, am[5]+pm1.y, am[6]+pm1.z, am[7]+pm1.w };
            const float xs[HEADS] = { as_[0]+ps0.x, as_[1]+ps0.y, as_[2]+ps0.z, as_[3]+ps0.w,
                                      as_[4]+ps1.x, as_[5]+ps1.y, as_[6]+ps1.z, as_[7]+ps1.w };

            float mu[HEADS], sg[HEADS];
            #pragma unroll
            for (int h = 0; h < HEADS; h++) {
                mu[h] = fmaxf(xm[h] + 1.0f, __expf(fminf(xm[h], 0.f)));
                sg[h] = fmaxf(xs[h] + 1.1f, __expf(fminf(xs[h], 0.f)) + 0.1f);
                acc[h] += mu[h];
            }

            const size_t p = (size_t)m * PROA + j0;
            float4* om = (float4*)(out_mu  + p * HEADS);
            float4* os = (float4*)(out_sig + p * HEADS);
            om[0] = make_float4(mu[0], mu[1], mu[2], mu[3]);
            om[1] = make_float4(mu[4], mu[5], mu[6], mu[7]);
            os[0] = make_float4(sg[0], sg[1], sg[2], sg[3]);
            os[1] = make_float4(sg[4], sg[5], sg[6], sg[7]);
        }

        // Deterministic reduction: warp butterfly, then cross-warp combine.
        #pragma unroll
        for (int s = 16; s > 0; s >>= 1) {
            #pragma unroll
            for (int h = 0; h < HEADS; h++)
                acc[h] += __shfl_xor_sync(0xFFFFFFFFu, acc[h], s);
        }
        if (lid == 0) {
            #pragma unroll
            for (int h = 0; h < HEADS; h++) swarp[wid][h] = acc[h];
        }
        __syncthreads();
        if (tid < HEADS) {
            float tsum = 0.f;
            #pragma unroll
            for (int w = 0; w < PAIR_THREADS / 32; w++) tsum += swarp[w][tid];
            g_ymol[(size_t)m * HEADS + tid] = tsum;
        }
        __syncthreads();   // protect swarp reuse next ma
    }
}

// ---------------------------------------------------------------------------
// Kernel 3: batch head.  y[b] = elu((0.001*sum_mol ymol) @ W1 + b1) @ W2 + b2
// ---------------------------------------------------------------------------
__global__ void final_kernel(const float* __restrict__ W1, const float* __restrict__ b1,
                             const float* __restrict__ W2, const float* __restrict__ b2,
                             float* __restrict__ out_y)
{
    int b = threadIdx.x;
    if (b >= BATCH) return;
    float y[HEADS];
    #pragma unroll
    for (int h = 0; h < HEADS; h++) y[h] = 0.f;
    for (int m = 0; m < MOLA; m++) {
        #pragma unroll
        for (int h = 0; h < HEADS; h++)
            y[h] += g_ymol[(b * MOLA + m) * HEADS + h];
    }
    #pragma unroll
    for (int h = 0; h < HEADS; h++) y[h] *= 0.001f;

    float outv = b2[0];
    #pragma unroll
    for (int j = 0; j < 2 * HEADS; j++) {
        float t = b1[j];
        #pragma unroll
        for (int h = 0; h < HEADS; h++)
            t = fmaf(y[h], W1[h * (2 * HEADS) + j], t);
        t = (t > 0.f) ? t : expm1f(t);           // plain elu (64 calls, keep precise)
        outv = fmaf(t, W2[j], outv);
    }
    out_y[b] = outv;
}

// ---------------------------------------------------------------------------
// Launch. Inputs (metadata order): mol_feats, pro_feats, spatial_feats,
// W_sigma, b_sigma, W_mu, b_mu, W1, b1, W2, b2, mol_index, pro_index, mol_batch.
// Indices are fully structured -> computed arithmetically, never read.
// Output: [mu (P*8) | sigma (P*8) | y (64)] float32.
// ---------------------------------------------------------------------------
extern "C" void kernel_launch(void* const* d_in, const int* in_sizes, int n_in,
                              void* d_out, int out_size)
{
    const float* mol_feats = (const float*)d_in[0];
    const float* pro_feats = (const float*)d_in[1];
    const float* spat      = (const float*)d_in[2];
    const float* Wsig      = (const float*)d_in[3];
    const float* bsig      = (const float*)d_in[4];
    const float* Wmu       = (const float*)d_in[5];
    const float* bmu       = (const float*)d_in[6];
    const float* W1        = (const float*)d_in[7];
    const float* b1        = (const float*)d_in[8];
    const float* W2        = (const float*)d_in[9];
    const float* b2        = (const float*)d_in[10];

    float* out_mu  = (float*)d_out;
    float* out_sig = out_mu + NPAIR * HEADS;
    float* out_y   = out_mu + 2 * NPAIR * HEADS;

    const int threadsTot = (NMOL + NPRO) * HEADS;        // 281,600
    proj_kernel<<<(threadsTot + 255) / 256, 256>>>(mol_feats, pro_feats, spat,
                                                   Wsig, bsig, Wmu, bmu);
    pairs_kernel<<<BATCH * NCHUNK, PAIR_THREADS>>>(out_mu, out_sig);
    final_kernel<<<1, BATCH>>>(W1, b1, W2, b2, out_y);
}

// round 9
// speedup vs baseline: 1.5235x; 1.5235x over previous
#include <cuda_runtime.h>
#include <math.h>

#define BATCH 64
#define MOLA  50
#define PROA  500
#define HID   32
#define HEADS 8
#define NMOL  (BATCH * MOLA)          // 3200
#define NPRO  (BATCH * PROA)          // 32000
#define NPAIR ((size_t)NMOL * PROA)   // 1,600,000

// Scratch (allocation-free rule: __device__ globals)
__device__ float g_Amu [NMOL * HEADS];
__device__ float g_Asig[NMOL * HEADS];
__device__ float g_Pmu [NPRO * HEADS];
__device__ float g_Psig[NPRO * HEADS];
__device__ float g_ymol[NMOL * HEADS];

// ---------------------------------------------------------------------------
// Kernel 1: per-atom projections. One thread per (row, head-half):
// 70,400 threads, 8 independent FMA chains each (4 mu + 4 sigma accumulators),
// 2x less redundant feature-load traffic than per-(row,head), dense float4
// stores (16B lane stride).
// ---------------------------------------------------------------------------
__global__ __launch_bounds__(256)
void proj_kernel(const float* __restrict__ mol_feats,
                 const float* __restrict__ pro_feats,
                 const float* __restrict__ spat,
                 const float* __restrict__ Wsig,
                 const float* __restrict__ bsig,
                 const float* __restrict__ Wmu,
                 const float* __restrict__ bmu)
{
    __shared__ float4 sWmu4[2 * HID * 2];    // [k][half] float4 layout, 1 KB
    __shared__ float4 sWsig4[2 * HID * 2];
    for (int i = threadIdx.x; i < 2 * HID * 2; i += blockDim.x) {
        sWmu4[i]  = ((const float4*)Wmu)[i];
        sWsig4[i] = ((const float4*)Wsig)[i];
    }
    __syncthreads();

    const int t   = blockIdx.x * blockDim.x + threadIdx.x;
    const int r   = t >> 1;
    const int sel = t & 1;                   // head half: 0 -> h0-3, 1 -> h4-7
    if (r >= NMOL + NPRO) return;

    const bool isMol = (r < NMOL);
    const int  j     = isMol ? r : (r - NMOL);

    float4 bm = ((const float4*)bmu)[sel];
    float4 bs = ((const float4*)bsig)[sel];
    float am0 = isMol ? bm.x : 0.f, am1 = isMol ? bm.y : 0.f;
    float am2 = isMol ? bm.z : 0.f, am3 = isMol ? bm.w : 0.f;
    float as0 = isMol ? bs.x : 0.f, as1 = isMol ? bs.y : 0.f;
    float as2 = isMol ? bs.z : 0.f, as3 = isMol ? bs.w : 0.f;

    // weight rows: mol uses k in [0,32), pro uses k in [32,64)
    const int wbase = (isMol ? 0 : HID * 2) + sel;

    const float4* fsrc = isMol ? (const float4*)(mol_feats + (size_t)r * HID)
                               : (const float4*)(pro_feats + (size_t)j * HID);
    const float4* ssrc = isMol ? (const float4*)nullptr
                               : (const float4*)(spat + (size_t)j * HID);

    #pragma unroll
    for (int c = 0; c < HID / 4; c++) {
        float4 f4 = fsrc[c];
        if (!isMol) {
            float4 s4 = ssrc[c];
            f4.x *= s4.x; f4.y *= s4.y; f4.z *= s4.z; f4.w *= s4.w;
        }
        const float fv[4] = { f4.x, f4.y, f4.z, f4.w };
        #pragma unroll
        for (int e = 0; e < 4; e++) {
            const int k = c * 4 + e;
            const float4 wm = sWmu4 [wbase + k * 2];
            const float4 ws = sWsig4[wbase + k * 2];
            am0 = fmaf(fv[e], wm.x, am0);
            am1 = fmaf(fv[e], wm.y, am1);
            am2 = fmaf(fv[e], wm.z, am2);
            am3 = fmaf(fv[e], wm.w, am3);
            as0 = fmaf(fv[e], ws.x, as0);
            as1 = fmaf(fv[e], ws.y, as1);
            as2 = fmaf(fv[e], ws.z, as2);
            as3 = fmaf(fv[e], ws.w, as3);
        }
    }

    const float4 vm = make_float4(am0, am1, am2, am3);
    const float4 vs = make_float4(as0, as1, as2, as3);
    if (isMol) {
        ((float4*)g_Amu )[(size_t)r * 2 + sel] = vm;
        ((float4*)g_Asig)[(size_t)r * 2 + sel] = vs;
    } else {
        ((float4*)g_Pmu )[(size_t)j * 2 + sel] = vm;
        ((float4*)g_Psig)[(size_t)j * 2 + sel] = vs;
    }
}

// ---------------------------------------------------------------------------
// Kernel 2: per-pair mu/sigma + per-mol-atom sum of mu.
// Block = (complex b, chunk of 5 mol atoms): 640 blocks x 256 threads.
// Work item v = q*2 + sel: pair q of the complex, head-half sel = tid&1.
// => every float4 store has 16B lane stride: fully dense STG.128 (full 32B
//    sectors, full 128B lines per instruction). Streaming (__stcs) stores.
// P-table staged in smem once per block (32 KB, float4[1000] per matrix).
// Branchless ELU: mu = max(x+1, exp(min(x,0))), sigma = max(x+1.1, exp(min(x,0))+0.1)
// ---------------------------------------------------------------------------
#define CHUNK_MOL 5
#define NCHUNK (MOLA / CHUNK_MOL)     // 10
#define PAIR_THREADS 256

__global__ __launch_bounds__(PAIR_THREADS)
void pairs_kernel(float* __restrict__ out_mu, float* __restrict__ out_sig)
{
    __shared__ float4 sPmu[PROA * 2];   // 16 KB
    __shared__ float4 sPsg[PROA * 2];   // 16 KB
    __shared__ float  swarp[PAIR_THREADS / 32][HEADS];

    const int b     = blockIdx.x / NCHUNK;
    const int chunk = blockIdx.x % NCHUNK;
    const int tid   = threadIdx.x;
    const int sel   = tid & 1;
    const int wid   = tid >> 5;
    const int lid   = tid & 31;

    // Stage the complex's P-tables (dense float4 copy).
    {
        const float4* gPm = (const float4*)(g_Pmu  + (size_t)b * PROA * HEADS);
        const float4* gPs = (const float4*)(g_Psig + (size_t)b * PROA * HEADS);
        #pragma unroll
        for (int v = tid; v < PROA * 2; v += PAIR_THREADS) {
            sPmu[v] = gPm[v];
            sPsg[v] = gPs[v];
        }
    }
    __syncthreads();

    #pragma unroll 1
    for (int ma = 0; ma < CHUNK_MOL; ma++) {
        const int m = b * MOLA + chunk * CHUNK_MOL + ma;

        // This lane's head-half of the mol-atom terms.
        const float4 a4 = ((const float4*)(g_Amu  + (size_t)m * HEADS))[sel];
        const float4 s4 = ((const float4*)(g_Asig + (size_t)m * HEADS))[sel];

        float acc0 = 0.f, acc1 = 0.f, acc2 = 0.f, acc3 = 0.f;

        const size_t obase = (size_t)m * (PROA * 2);   // float4 index base
        float4* __restrict__ om = (float4*)out_mu  + obase;
        float4* __restrict__ os = (float4*)out_sig + obase;

        #pragma unroll
        for (int it = 0; it < (PROA * 2 + PAIR_THREADS - 1) / PAIR_THREADS; it++) {
            const int v = it * PAIR_THREADS + tid;
            if (v < PROA * 2) {
                const float4 pm = sPmu[v];
                const float4 ps = sPsg[v];

                const float xm0 = a4.x + pm.x, xm1 = a4.y + pm.y;
                const float xm2 = a4.z + pm.z, xm3 = a4.w + pm.w;
                const float xs0 = s4.x + ps.x, xs1 = s4.y + ps.y;
                const float xs2 = s4.z + ps.z, xs3 = s4.w + ps.w;

                const float mu0 = fmaxf(xm0 + 1.0f, __expf(fminf(xm0, 0.f)));
                const float mu1 = fmaxf(xm1 + 1.0f, __expf(fminf(xm1, 0.f)));
                const float mu2 = fmaxf(xm2 + 1.0f, __expf(fminf(xm2, 0.f)));
                const float mu3 = fmaxf(xm3 + 1.0f, __expf(fminf(xm3, 0.f)));
                const float sg0 = fmaxf(xs0 + 1.1f, __expf(fminf(xs0, 0.f)) + 0.1f);
                const float sg1 = fmaxf(xs1 + 1.1f, __expf(fminf(xs1, 0.f)) + 0.1f);
                const float sg2 = fmaxf(xs2 + 1.1f, __expf(fminf(xs2, 0.f)) + 0.1f);
                const float sg3 = fmaxf(xs3 + 1.1f, __expf(fminf(xs3, 0.f)) + 0.1f);

                acc0 += mu0; acc1 += mu1; acc2 += mu2; acc3 += mu3;

                __stcs(om + v, make_float4(mu0, mu1, mu2, mu3));
                __stcs(os + v, make_float4(sg0, sg1, sg2, sg3));
            }
        }

        // Deterministic reduction. Same-parity butterfly (strides 16,8,4,2):
        // lane 0 ends with heads 0-3 summed over all even lanes' pairs,
        // lane 1 with heads 4-7 over all odd lanes' pairs.
        #pragma unroll
        for (int s = 16; s > 1; s >>= 1) {
            acc0 += __shfl_xor_sync(0xFFFFFFFFu, acc0, s);
            acc1 += __shfl_xor_sync(0xFFFFFFFFu, acc1, s);
            acc2 += __shfl_xor_sync(0xFFFFFFFFu, acc2, s);
            acc3 += __shfl_xor_sync(0xFFFFFFFFu, acc3, s);
        }
        if (lid < 2) {
            swarp[wid][lid * 4 + 0] = acc0;
            swarp[wid][lid * 4 + 1] = acc1;
            swarp[wid][lid * 4 + 2] = acc2;
            swarp[wid][lid * 4 + 3] = acc3;
        }
        __syncthreads();
        if (tid < HEADS) {
            float tsum = 0.f;
            #pragma unroll
            for (int w = 0; w < PAIR_THREADS / 32; w++) tsum += swarp[w][tid];
            g_ymol[(size_t)m * HEADS + tid] = tsum;
        }
        __syncthreads();   // protect swarp reuse next ma
    }
}

// ---------------------------------------------------------------------------
// Kernel 3: batch head.  y[b] = elu((0.001*sum_mol ymol) @ W1 + b1) @ W2 + b2
// Phase 1: 512 threads (b,h) sum the 50 mol atoms; phase 2: 64 threads MLP.
// ---------------------------------------------------------------------------
__global__ __launch_bounds__(512)
void final_kernel(const float* __restrict__ W1, const float* __restrict__ b1,
                  const float* __restrict__ W2, const float* __restrict__ b2,
                  float* __restrict__ out_y)
{
    __shared__ float sy[BATCH][HEADS];
    const int tid = threadIdx.x;
    {
        const int b = tid >> 3;
        const int h = tid & 7;
        float acc = 0.f;
        #pragma unroll 5
        for (int m = 0; m < MOLA; m++)
            acc += g_ymol[((size_t)b * MOLA + m) * HEADS + h];
        sy[b][h] = acc * 0.001f;
    }
    __syncthreads();
    if (tid < BATCH) {
        const int b = tid;
        float y[HEADS];
        #pragma unroll
        for (int h = 0; h < HEADS; h++) y[h] = sy[b][h];
        float outv = b2[0];
        #pragma unroll
        for (int j = 0; j < 2 * HEADS; j++) {
            float t = b1[j];
            #pragma unroll
            for (int h = 0; h < HEADS; h++)
                t = fmaf(y[h], W1[h * (2 * HEADS) + j], t);
            t = (t > 0.f) ? t : expm1f(t);           // plain elu (64 calls, keep precise)
            outv = fmaf(t, W2[j], outv);
        }
        out_y[b] = outv;
    }
}

// ---------------------------------------------------------------------------
// Launch. Inputs (metadata order): mol_feats, pro_feats, spatial_feats,
// W_sigma, b_sigma, W_mu, b_mu, W1, b1, W2, b2, mol_index, pro_index, mol_batch.
// Indices are fully structured -> computed arithmetically, never read.
// Output: [mu (P*8) | sigma (P*8) | y (64)] float32.
// ---------------------------------------------------------------------------
extern "C" void kernel_launch(void* const* d_in, const int* in_sizes, int n_in,
                              void* d_out, int out_size)
{
    const float* mol_feats = (const float*)d_in[0];
    const float* pro_feats = (const float*)d_in[1];
    const float* spat      = (const float*)d_in[2];
    const float* Wsig      = (const float*)d_in[3];
    const float* bsig      = (const float*)d_in[4];
    const float* Wmu       = (const float*)d_in[5];
    const float* bmu       = (const float*)d_in[6];
    const float* W1        = (const float*)d_in[7];
    const float* b1        = (const float*)d_in[8];
    const float* W2        = (const float*)d_in[9];
    const float* b2        = (const float*)d_in[10];

    float* out_mu  = (float*)d_out;
    float* out_sig = out_mu + NPAIR * HEADS;
    float* out_y   = out_mu + 2 * NPAIR * HEADS;

    const int threadsTot = (NMOL + NPRO) * 2;            // 70,400
    proj_kernel<<<(threadsTot + 255) / 256, 256>>>(mol_feats, pro_feats, spat,
                                                   Wsig, bsig, Wmu, bmu);
    pairs_kernel<<<BATCH * NCHUNK, PAIR_THREADS>>>(out_mu, out_sig);
    final_kernel<<<1, 512>>>(W1, b1, W2, b2, out_y);
}